// round 4
// baseline (speedup 1.0000x reference)
#include <cuda_runtime.h>
#include <math.h>

#define HW 4096
#define CHW 1048576
#define EPSV 1e-5f

// ---------------- scratch (device globals; no runtime allocation) ----------------
// Lifetime-aliased buffers:
//   g_bufA: h1 (conv1+bn1 out, kernels 2-3)  -> tln (LN out, kernels 5-6 and 9-10)
//   g_bufB: h2 (dw+bn2 out, kernels 3-4)     -> attno (attn out pre-proj, kernels 7-8)
__device__ float g_bn1s[256], g_bn1h[256], g_bn2s[256], g_bn2h[256];
__device__ float g_bufA[16777216];
__device__ float g_bufB[16777216];
__device__ float g_x1[16777216];     // conv residual sum, NCHW (kernels 4-8)
__device__ float g_x2[16777216];     // attn residual sum, NCHW (kernels 8-11)
__device__ float g_qkv[50331648];    // [win][3][4][d=64][tok=64] (kernels 6-7)
__device__ float g_t1[67108864];     // mlp hidden, [1024, 65536] (kernels 10-11)

__device__ __forceinline__ float geluf(float x) {
    return 0.5f * x * (1.0f + erff(x * 0.7071067811865476f));
}

// ---------------- prep: fold conv bias + BN into scale/shift ----------------
__global__ void k_prep(const float* c1b, const float* g1, const float* b1,
                       const float* m1, const float* v1, const float* dwb,
                       const float* g2, const float* b2, const float* m2, const float* v2) {
    int c = threadIdx.x;
    float inv1 = g1[c] * rsqrtf(v1[c] + EPSV);
    g_bn1s[c] = inv1;
    g_bn1h[c] = c1b[c] * inv1 + b1[c] - m1[c] * inv1;
    float inv2 = g2[c] * rsqrtf(v2[c] + EPSV);
    g_bn2s[c] = inv2;
    g_bn2h[c] = dwb[c] * inv2 + b2[c] - m2[c] * inv2;
}

// ---------------- GEMM variant 1: X is [K, N] with row stride ldX (channel-major) ----
// Out[o,n] = sum_k A[o,k] * X[k,n]; mode 0: affine (P0 scale, P1 shift)
//                                   mode 1: + P0[o] bias + Res[idx]
__global__ __launch_bounds__(256) void k_gemm_cn(
    const float* __restrict__ A, const float* __restrict__ X,
    float* __restrict__ Out, const float* __restrict__ Res,
    const float* __restrict__ P0, const float* __restrict__ P1,
    int K, long long ldX, long long bsX, long long ldO, long long bsO, int mode)
{
    __shared__ float As[2048];
    __shared__ float Bs[2048];
    int tid = threadIdx.x;
    int m0 = blockIdx.x * 128, n0 = blockIdx.y * 128;
    long long zX = (long long)blockIdx.z * bsX;
    int ty = tid >> 4, tx = tid & 15;
    float acc[8][8];
#pragma unroll
    for (int i = 0; i < 8; i++)
#pragma unroll
        for (int j = 0; j < 8; j++) acc[i][j] = 0.f;

    for (int k0 = 0; k0 < K; k0 += 16) {
#pragma unroll
        for (int u = 0; u < 2; u++) {
            int slot = tid * 2 + u;
            int m = slot >> 2, kq = slot & 3;
            float4 v = *(const float4*)&A[(long long)(m0 + m) * K + k0 + kq * 4];
            As[(kq * 4 + 0) * 128 + m] = v.x;
            As[(kq * 4 + 1) * 128 + m] = v.y;
            As[(kq * 4 + 2) * 128 + m] = v.z;
            As[(kq * 4 + 3) * 128 + m] = v.w;
        }
#pragma unroll
        for (int u = 0; u < 2; u++) {
            int slot = tid + u * 256;
            int kk = slot >> 5, nq = slot & 31;
            float4 v = *(const float4*)&X[zX + (long long)(k0 + kk) * ldX + n0 + nq * 4];
            *(float4*)&Bs[kk * 128 + nq * 4] = v;
        }
        __syncthreads();
#pragma unroll
        for (int kk = 0; kk < 16; kk++) {
            float a[8], b[8];
            *(float4*)&a[0] = *(float4*)&As[kk * 128 + ty * 8];
            *(float4*)&a[4] = *(float4*)&As[kk * 128 + ty * 8 + 4];
            *(float4*)&b[0] = *(float4*)&Bs[kk * 128 + tx * 8];
            *(float4*)&b[4] = *(float4*)&Bs[kk * 128 + tx * 8 + 4];
#pragma unroll
            for (int i = 0; i < 8; i++)
#pragma unroll
                for (int j = 0; j < 8; j++) acc[i][j] = fmaf(a[i], b[j], acc[i][j]);
        }
        __syncthreads();
    }
    long long zO = (long long)blockIdx.z * bsO;
#pragma unroll
    for (int i = 0; i < 8; i++) {
        int o = m0 + ty * 8 + i;
        float s = (mode == 0) ? P0[o] : 1.0f;
        float h = (mode == 0) ? P1[o] : P0[o];
#pragma unroll
        for (int jq = 0; jq < 2; jq++) {
            long long idx = zO + (long long)o * ldO + n0 + tx * 8 + jq * 4;
            float4 v;
            v.x = acc[i][jq * 4 + 0] * s + h;
            v.y = acc[i][jq * 4 + 1] * s + h;
            v.z = acc[i][jq * 4 + 2] * s + h;
            v.w = acc[i][jq * 4 + 3] * s + h;
            if (mode == 1) {
                float4 r = *(const float4*)&Res[idx];
                v.x += r.x; v.y += r.y; v.z += r.z; v.w += r.w;
            }
            *(float4*)&Out[idx] = v;
        }
    }
}

// ---------------- GEMM variant 2: T is [Ntok, K] row-major (token-major) ----------
// Out[o,n] = sum_k A[o,k] * T[n,k]
// mode 0: QKV -> g_qkv ([win][s][h][d][tok]), + Bias
// mode 1: PROJ -> g_x2 (NCHW via window-reverse), + Bias + g_x1 residual
// mode 2: MLP1 -> g_t1 ([o, n]), gelu(val + Bias)
__global__ __launch_bounds__(256) void k_gemm_tok(
    const float* __restrict__ A, const float* __restrict__ T,
    const float* __restrict__ Bias, int K, int mode)
{
    __shared__ float As[2048];
    __shared__ float Bs[2048];
    int tid = threadIdx.x;
    int m0 = blockIdx.x * 128, n0 = blockIdx.y * 128;
    int ty = tid >> 4, tx = tid & 15;
    float acc[8][8];
#pragma unroll
    for (int i = 0; i < 8; i++)
#pragma unroll
        for (int j = 0; j < 8; j++) acc[i][j] = 0.f;

    for (int k0 = 0; k0 < K; k0 += 16) {
#pragma unroll
        for (int u = 0; u < 2; u++) {
            int slot = tid * 2 + u;
            int m = slot >> 2, kq = slot & 3;
            float4 v = *(const float4*)&A[(long long)(m0 + m) * K + k0 + kq * 4];
            As[(kq * 4 + 0) * 128 + m] = v.x;
            As[(kq * 4 + 1) * 128 + m] = v.y;
            As[(kq * 4 + 2) * 128 + m] = v.z;
            As[(kq * 4 + 3) * 128 + m] = v.w;
        }
#pragma unroll
        for (int u = 0; u < 2; u++) {
            int slot = tid * 2 + u;
            int n = slot >> 2, kq = slot & 3;
            float4 v = *(const float4*)&T[(long long)(n0 + n) * K + k0 + kq * 4];
            Bs[(kq * 4 + 0) * 128 + n] = v.x;
            Bs[(kq * 4 + 1) * 128 + n] = v.y;
            Bs[(kq * 4 + 2) * 128 + n] = v.z;
            Bs[(kq * 4 + 3) * 128 + n] = v.w;
        }
        __syncthreads();
#pragma unroll
        for (int kk = 0; kk < 16; kk++) {
            float a[8], b[8];
            *(float4*)&a[0] = *(float4*)&As[kk * 128 + ty * 8];
            *(float4*)&a[4] = *(float4*)&As[kk * 128 + ty * 8 + 4];
            *(float4*)&b[0] = *(float4*)&Bs[kk * 128 + tx * 8];
            *(float4*)&b[4] = *(float4*)&Bs[kk * 128 + tx * 8 + 4];
#pragma unroll
            for (int i = 0; i < 8; i++)
#pragma unroll
                for (int j = 0; j < 8; j++) acc[i][j] = fmaf(a[i], b[j], acc[i][j]);
        }
        __syncthreads();
    }
#pragma unroll
    for (int i = 0; i < 8; i++) {
        int o = m0 + ty * 8 + i;
        float bia = Bias[o];
#pragma unroll
        for (int jq = 0; jq < 2; jq++) {
            int nb = n0 + tx * 8 + jq * 4;
            float4 v;
            v.x = acc[i][jq * 4 + 0] + bia;
            v.y = acc[i][jq * 4 + 1] + bia;
            v.z = acc[i][jq * 4 + 2] + bia;
            v.w = acc[i][jq * 4 + 3] + bia;
            if (mode == 0) {
                int win = nb >> 6, j = nb & 63;
                int s = o >> 8, rr = o & 255, hh = rr >> 6, d = rr & 63;
                long long idx = ((((long long)win * 3 + s) * 4 + hh) * 64 + d) * 64 + j;
                *(float4*)&g_qkv[idx] = v;
            } else if (mode == 1) {
                int win = nb >> 6, j = nb & 63;
                int b = win >> 6, widx = win & 63;
                int h = ((widx >> 3) << 3) + (j >> 3);
                int w = ((widx & 7) << 3) + (j & 7);
                long long idx = (long long)b * CHW + (long long)o * HW + h * 64 + w;
                float4 r = *(const float4*)&g_x1[idx];
                v.x += r.x; v.y += r.y; v.z += r.z; v.w += r.w;
                *(float4*)&g_x2[idx] = v;
            } else {
                long long idx = (long long)o * 65536 + nb;
                v.x = geluf(v.x); v.y = geluf(v.y); v.z = geluf(v.z); v.w = geluf(v.w);
                *(float4*)&g_t1[idx] = v;
            }
        }
    }
}

// ---------------- depthwise 3x3 + folded BN2 ----------------
__global__ void k_dw(const float* __restrict__ in, const float* __restrict__ w,
                     float* __restrict__ out) {
    long long idx = (long long)blockIdx.x * 256 + threadIdx.x;
    int wi = (int)(idx & 63);
    int hi = (int)((idx >> 6) & 63);
    int c = (int)((idx >> 12) & 255);
    long long pb = idx - (hi * 64 + wi);
    const float* wp = &w[c * 9];
    float acc = 0.f;
#pragma unroll
    for (int ky = 0; ky < 3; ky++) {
        int h2 = hi + ky - 1;
        if (h2 < 0 || h2 > 63) continue;
#pragma unroll
        for (int kx = 0; kx < 3; kx++) {
            int w2 = wi + kx - 1;
            if (w2 < 0 || w2 > 63) continue;
            acc += wp[ky * 3 + kx] * in[pb + h2 * 64 + w2];
        }
    }
    out[idx] = acc * g_bn2s[c] + g_bn2h[c];
}

// ---------------- LayerNorm over C=256 -> token-major output ----------------
// mode 0: window-ordered tokens (block = window), mode 1: row-ordered (block = (b,h))
__global__ void k_ln(const float* __restrict__ xin, const float* __restrict__ g,
                     const float* __restrict__ bta, float* __restrict__ out, int mode)
{
    extern __shared__ float sm[];
    float* s = sm;              // 256*65 = 16640
    float* red = sm + 16640;    // 512
    float* mu = red + 512;      // 64
    float* rs = mu + 64;        // 64
    int tid = threadIdx.x;
    int blk = blockIdx.x;
    int b = blk >> 6, q = blk & 63;

    for (int i = tid; i < 16384; i += 256) {
        int c = i >> 6, tok = i & 63;
        long long sp;
        if (mode == 0)
            sp = (long long)b * CHW + (long long)c * HW +
                 (((q >> 3) << 3) + (tok >> 3)) * 64 + ((q & 7) << 3) + (tok & 7);
        else
            sp = (long long)b * CHW + (long long)c * HW + q * 64 + tok;
        s[c * 65 + tok] = xin[sp];
    }
    __syncthreads();
    {
        int tok = tid & 63, part = tid >> 6;
        float sum = 0.f, sq = 0.f;
        for (int c = part * 64; c < part * 64 + 64; c++) {
            float v = s[c * 65 + tok];
            sum += v; sq += v * v;
        }
        red[tid] = sum;
        red[256 + tid] = sq;
    }
    __syncthreads();
    if (tid < 64) {
        float S = red[tid] + red[64 + tid] + red[128 + tid] + red[192 + tid];
        float Q = red[256 + tid] + red[320 + tid] + red[384 + tid] + red[448 + tid];
        float m = S * 0.00390625f;
        float var = Q * 0.00390625f - m * m;
        mu[tid] = m;
        rs[tid] = rsqrtf(var + EPSV);
    }
    __syncthreads();
    long long ob = (long long)blk * 16384;
    for (int i = tid; i < 16384; i += 256) {
        int t2 = i >> 8, c = i & 255;
        out[ob + i] = (s[c * 65 + t2] - mu[t2]) * rs[t2] * g[c] + bta[c];
    }
}

// ---------------- attention: one block per (window, head) ----------------
// Output written to g_bufB ("attno" role): [win*64+tok, 256] token-major.
__global__ __launch_bounds__(256) void k_attn() {
    extern __shared__ float sm[];
    float* qs = sm;                 // [d][tok], 4096
    float* ks = sm + 4096;          // 4096
    float* vs = sm + 8192;          // [d*65+tok], 4160 (padded)
    float* ss = sm + 12352;         // [i*65+j], 4160 (padded)
    int tid = threadIdx.x;
    int win = blockIdx.x, hh = blockIdx.y;
    long long bq = (((long long)win * 3 + 0) * 4 + hh) * 4096;
    long long bk = (((long long)win * 3 + 1) * 4 + hh) * 4096;
    long long bv = (((long long)win * 3 + 2) * 4 + hh) * 4096;
    for (int i = tid; i < 1024; i += 256) {
        ((float4*)qs)[i] = *(const float4*)&g_qkv[bq + (long long)i * 4];
        ((float4*)ks)[i] = *(const float4*)&g_qkv[bk + (long long)i * 4];
    }
    for (int i = tid; i < 4096; i += 256)
        vs[(i >> 6) * 65 + (i & 63)] = g_qkv[bv + i];
    __syncthreads();

    int ti = tid >> 4, tj = tid & 15;
    int i0 = ti * 4, j0 = tj * 4;
    {
        float acc[4][4];
#pragma unroll
        for (int r = 0; r < 4; r++)
#pragma unroll
            for (int c = 0; c < 4; c++) acc[r][c] = 0.f;
        for (int d = 0; d < 64; d++) {
            float4 qv = *(float4*)&qs[d * 64 + i0];
            float4 kv = *(float4*)&ks[d * 64 + j0];
            float qa[4] = {qv.x, qv.y, qv.z, qv.w};
            float ka[4] = {kv.x, kv.y, kv.z, kv.w};
#pragma unroll
            for (int r = 0; r < 4; r++)
#pragma unroll
                for (int c = 0; c < 4; c++) acc[r][c] = fmaf(qa[r], ka[c], acc[r][c]);
        }
#pragma unroll
        for (int r = 0; r < 4; r++)
#pragma unroll
            for (int c = 0; c < 4; c++)
                ss[(i0 + r) * 65 + j0 + c] = acc[r][c] * 0.125f;
    }
    __syncthreads();
    if (tid < 64) {
        float mx = -3.4e38f;
        for (int j = 0; j < 64; j++) mx = fmaxf(mx, ss[tid * 65 + j]);
        float sum = 0.f;
        for (int j = 0; j < 64; j++) {
            float e = expf(ss[tid * 65 + j] - mx);
            ss[tid * 65 + j] = e;
            sum += e;
        }
        float inv = 1.f / sum;
        for (int j = 0; j < 64; j++) ss[tid * 65 + j] *= inv;
    }
    __syncthreads();
    {
        float acc[4][4];
#pragma unroll
        for (int r = 0; r < 4; r++)
#pragma unroll
            for (int c = 0; c < 4; c++) acc[r][c] = 0.f;
        for (int j = 0; j < 64; j++) {
            float p[4], vv[4];
#pragma unroll
            for (int r = 0; r < 4; r++) p[r] = ss[(i0 + r) * 65 + j];
#pragma unroll
            for (int c = 0; c < 4; c++) vv[c] = vs[(j0 + c) * 65 + j];
#pragma unroll
            for (int r = 0; r < 4; r++)
#pragma unroll
                for (int c = 0; c < 4; c++) acc[r][c] = fmaf(p[r], vv[c], acc[r][c]);
        }
#pragma unroll
        for (int r = 0; r < 4; r++) {
            float4 v = make_float4(acc[r][0], acc[r][1], acc[r][2], acc[r][3]);
            long long oi = ((long long)win * 64 + i0 + r) * 256 + hh * 64 + j0;
            *(float4*)&g_bufB[oi] = v;
        }
    }
}

// ---------------- host ----------------
extern "C" void kernel_launch(void* const* d_in, const int* in_sizes, int n_in,
                              void* d_out, int out_size) {
    const float* x       = (const float*)d_in[0];
    const float* conv1_w = (const float*)d_in[1];
    const float* conv1_b = (const float*)d_in[2];
    const float* bn1_g   = (const float*)d_in[3];
    const float* bn1_b   = (const float*)d_in[4];
    const float* bn1_m   = (const float*)d_in[5];
    const float* bn1_v   = (const float*)d_in[6];
    const float* dw_w    = (const float*)d_in[7];
    const float* dw_b    = (const float*)d_in[8];
    const float* bn2_g   = (const float*)d_in[9];
    const float* bn2_b   = (const float*)d_in[10];
    const float* bn2_m   = (const float*)d_in[11];
    const float* bn2_v   = (const float*)d_in[12];
    const float* conv3_w = (const float*)d_in[13];
    const float* conv3_b = (const float*)d_in[14];
    const float* ln1_g   = (const float*)d_in[15];
    const float* ln1_b   = (const float*)d_in[16];
    const float* qkv_w   = (const float*)d_in[17];
    const float* qkv_b   = (const float*)d_in[18];
    const float* proj_w  = (const float*)d_in[19];
    const float* proj_b  = (const float*)d_in[20];
    const float* ln2_g   = (const float*)d_in[21];
    const float* ln2_b   = (const float*)d_in[22];
    const float* mlp_w1  = (const float*)d_in[23];
    const float* mlp_b1  = (const float*)d_in[24];
    const float* mlp_w2  = (const float*)d_in[25];
    const float* mlp_b2  = (const float*)d_in[26];

    float *bufA, *bufB, *x1, *x2, *t1, *bn1s, *bn1h;
    cudaGetSymbolAddress((void**)&bufA, g_bufA);
    cudaGetSymbolAddress((void**)&bufB, g_bufB);
    cudaGetSymbolAddress((void**)&x1,   g_x1);
    cudaGetSymbolAddress((void**)&x2,   g_x2);
    cudaGetSymbolAddress((void**)&t1,   g_t1);
    cudaGetSymbolAddress((void**)&bn1s, g_bn1s);
    cudaGetSymbolAddress((void**)&bn1h, g_bn1h);

    const int smemLN = 17280 * 4;  // 69120 B
    const int smemAT = 16512 * 4;  // 66048 B
    cudaFuncSetAttribute(k_ln,   cudaFuncAttributeMaxDynamicSharedMemorySize, smemLN);
    cudaFuncSetAttribute(k_attn, cudaFuncAttributeMaxDynamicSharedMemorySize, smemAT);

    // 1. BN folding
    k_prep<<<1, 256>>>(conv1_b, bn1_g, bn1_b, bn1_m, bn1_v,
                       dw_b, bn2_g, bn2_b, bn2_m, bn2_v);
    // 2. conv1 (1x1) + BN1 -> bufA (h1)
    k_gemm_cn<<<dim3(2, 32, 16), 256>>>(conv1_w, x, bufA, nullptr, bn1s, bn1h,
                                        256, 4096LL, (long long)CHW, 4096LL, (long long)CHW, 0);
    // 3. depthwise 3x3 + BN2 -> bufB (h2)
    k_dw<<<65536, 256>>>(bufA, dw_w, bufB);
    // 4. conv3 (1x1) + bias + residual(x) -> x1
    k_gemm_cn<<<dim3(2, 32, 16), 256>>>(conv3_w, bufB, x1, x, conv3_b, nullptr,
                                        256, 4096LL, (long long)CHW, 4096LL, (long long)CHW, 1);
    // 5. LN1 (window-ordered tokens) -> bufA (tln)
    k_ln<<<1024, 256, smemLN>>>(x1, ln1_g, ln1_b, bufA, 0);
    // 6. QKV GEMM -> g_qkv
    k_gemm_tok<<<dim3(6, 512), 256>>>(qkv_w, bufA, qkv_b, 256, 0);
    // 7. attention per (window, head) -> bufB (attno)
    k_attn<<<dim3(1024, 4), 256, smemAT>>>();
    // 8. proj GEMM + residual(x1) -> x2 (NCHW)
    k_gemm_tok<<<dim3(2, 512), 256>>>(proj_w, bufB, proj_b, 256, 1);
    // 9. LN2 (row-ordered tokens) -> bufA (tln)
    k_ln<<<1024, 256, smemLN>>>(x2, ln2_g, ln2_b, bufA, 1);
    // 10. MLP1 + GELU -> t1 [1024, 65536]
    k_gemm_tok<<<dim3(8, 512), 256>>>(mlp_w1, bufA, mlp_b1, 256, 2);
    // 11. MLP2 + bias + residual(x2) -> out (NCHW)
    k_gemm_cn<<<dim3(2, 32, 16), 256>>>(mlp_w2, t1, (float*)d_out, x2, mlp_b2, nullptr,
                                        1024, 65536LL, 4096LL, 4096LL, (long long)CHW, 1);
}

// round 6
// speedup vs baseline: 2.5334x; 2.5334x over previous
#include <cuda_runtime.h>
#include <cuda_bf16.h>
#include <math.h>

#define HW 4096
#define CHW 1048576
#define EPSV 1e-5f
#define LDK 40   // padded smem row stride in halves (conflict-free for pad=8)

// ---------------- scratch (device globals; no runtime allocation) ----------------
__device__ float g_bn1s[256], g_bn1h[256], g_bn2s[256], g_bn2h[256];
__device__ float g_x1[16777216];               // conv residual sum, NCHW fp32
__device__ float g_x2[16777216];               // attn residual sum, NCHW fp32
__device__ float g_qkv[50331648];              // [win][3][4][d=64][tok=64] fp32
__device__ __nv_bfloat16 gb_xt[16777216];      // x token-major bf16 [tok][256]
__device__ __nv_bfloat16 gb_a[16777216];       // h1 token-major bf16
__device__ __nv_bfloat16 gb_b[16777216];       // h2 token-major bf16
__device__ __nv_bfloat16 gb_tok[16777216];     // tln / attno token-major bf16 (sequential reuse)
__device__ __nv_bfloat16 gb_t1[67108864];      // mlp hidden bf16 [tok][1024]
__device__ __nv_bfloat16 gb_w[917504];         // all weights bf16

__device__ __forceinline__ float geluf(float x) {
    return 0.5f * x * (1.0f + erff(x * 0.7071067811865476f));
}

__device__ __forceinline__ void mma_bf16(float* c, unsigned a0, unsigned a1,
                                         unsigned a2, unsigned a3,
                                         unsigned b0, unsigned b1) {
    asm volatile(
        "mma.sync.aligned.m16n8k16.row.col.f32.bf16.bf16.f32 "
        "{%0,%1,%2,%3}, {%4,%5,%6,%7}, {%8,%9}, {%0,%1,%2,%3};\n"
        : "+f"(c[0]), "+f"(c[1]), "+f"(c[2]), "+f"(c[3])
        : "r"(a0), "r"(a1), "r"(a2), "r"(a3), "r"(b0), "r"(b1));
}

// ---------------- prep: fold conv bias + BN into scale/shift ----------------
__global__ void k_prep(const float* c1b, const float* g1, const float* b1,
                       const float* m1, const float* v1, const float* dwb,
                       const float* g2, const float* b2, const float* m2, const float* v2) {
    int c = threadIdx.x;
    float inv1 = g1[c] * rsqrtf(v1[c] + EPSV);
    g_bn1s[c] = inv1;
    g_bn1h[c] = c1b[c] * inv1 + b1[c] - m1[c] * inv1;
    float inv2 = g2[c] * rsqrtf(v2[c] + EPSV);
    g_bn2s[c] = inv2;
    g_bn2h[c] = dwb[c] * inv2 + b2[c] - m2[c] * inv2;
}

// ---------------- fp32 -> bf16 convert ----------------
__global__ void k_cvt(const float* __restrict__ s, __nv_bfloat16* __restrict__ d, int n) {
    int i = blockIdx.x * 256 + threadIdx.x;
    if (i < n) d[i] = __float2bfloat16(s[i]);
}

// ---------------- x NCHW fp32 -> token-major bf16 transpose ----------------
__global__ __launch_bounds__(256) void k_tx(const float* __restrict__ x,
                                            __nv_bfloat16* __restrict__ xt) {
    __shared__ float s[32][33];
    int b = blockIdx.z, cg = blockIdx.y * 32, pg = blockIdx.x * 32;
    int tid = threadIdx.x;
    for (int i = tid; i < 1024; i += 256) {
        int c = i >> 5, p = i & 31;
        s[c][p] = x[(long long)b * CHW + (long long)(cg + c) * HW + pg + p];
    }
    __syncthreads();
    for (int i = tid; i < 1024; i += 256) {
        int p = i >> 5, c = i & 31;
        xt[((long long)(b * 4096 + pg + p)) * 256 + cg + c] = __float2bfloat16(s[c][p]);
    }
}

// ---------------- unified bf16 tensor-core GEMM ----------------
// Out[o,n] = sum_k A[o,k] * B[n,k], A bf16 [M,K] row-major, B bf16 token-major [N,K].
// Tiles: BM=128, BN=128, BK=32. 8 warps (2x4), warp tile 64x32, mma m16n8k16.
// modes: 0 conv1 (affine P0/P1 -> bf16 OutH[n*ldo+o])
//        1 conv3 (+P0 bias + Res NCHW -> fp32 OutF NCHW)
//        2 qkv   (+P0 -> fp32 g_qkv scatter)
//        3 proj  (+P0 + Res x1, window-reverse -> fp32 OutF NCHW)
//        4 mlp1  (gelu(v+P0) -> bf16 OutH[n*ldo+o])
//        5 mlp2  (+P0 + Res x2 -> fp32 OutF NCHW)
__global__ __launch_bounds__(256) void k_mm(
    const __nv_bfloat16* __restrict__ A, const __nv_bfloat16* __restrict__ B,
    int K, int mode, const float* __restrict__ P0, const float* __restrict__ P1,
    const float* __restrict__ Res, float* __restrict__ OutF,
    __nv_bfloat16* __restrict__ OutH, int ldo)
{
    __shared__ __nv_bfloat16 sA[128 * LDK];
    __shared__ __nv_bfloat16 sB[128 * LDK];
    int tid = threadIdx.x, wid = tid >> 5, lane = tid & 31;
    int m0 = blockIdx.x * 128, n0 = blockIdx.y * 128;
    int wm = wid >> 2, wn = wid & 3;           // warp grid 2x4
    int g = lane >> 2, thc = lane & 3;

    float acc[4][4][4];
#pragma unroll
    for (int i = 0; i < 4; i++)
#pragma unroll
        for (int j = 0; j < 4; j++)
#pragma unroll
            for (int r = 0; r < 4; r++) acc[i][j][r] = 0.f;

    int lrow = tid >> 1, lq8 = (tid & 1) * 16;   // halves offset 0 or 16
    const __nv_bfloat16* pa = A + (long long)(m0 + lrow) * K + lq8;
    const __nv_bfloat16* pb = B + (long long)(n0 + lrow) * K + lq8;
    int sOff = lrow * LDK + lq8;

    const int KT = K >> 5;
    uint4 ra0 = *(const uint4*)(pa);
    uint4 ra1 = *(const uint4*)(pa + 8);
    uint4 rb0 = *(const uint4*)(pb);
    uint4 rb1 = *(const uint4*)(pb + 8);

    for (int kt = 0; kt < KT; kt++) {
        *(uint4*)&sA[sOff] = ra0;
        *(uint4*)&sA[sOff + 8] = ra1;
        *(uint4*)&sB[sOff] = rb0;
        *(uint4*)&sB[sOff + 8] = rb1;
        __syncthreads();
        if (kt + 1 < KT) {
            const __nv_bfloat16* qa = pa + (kt + 1) * 32;
            const __nv_bfloat16* qb = pb + (kt + 1) * 32;
            ra0 = *(const uint4*)(qa);  ra1 = *(const uint4*)(qa + 8);
            rb0 = *(const uint4*)(qb);  rb1 = *(const uint4*)(qb + 8);
        }
#pragma unroll
        for (int ks = 0; ks < 2; ks++) {
            unsigned af[4][4], bf[4][2];
            int kc = ks * 16 + thc * 2;
#pragma unroll
            for (int mi = 0; mi < 4; mi++) {
                int rb_ = wm * 64 + mi * 16 + g;
                af[mi][0] = *(const unsigned*)&sA[rb_ * LDK + kc];
                af[mi][1] = *(const unsigned*)&sA[(rb_ + 8) * LDK + kc];
                af[mi][2] = *(const unsigned*)&sA[rb_ * LDK + kc + 8];
                af[mi][3] = *(const unsigned*)&sA[(rb_ + 8) * LDK + kc + 8];
            }
#pragma unroll
            for (int nj = 0; nj < 4; nj++) {
                int rn = wn * 32 + nj * 8 + g;
                bf[nj][0] = *(const unsigned*)&sB[rn * LDK + kc];
                bf[nj][1] = *(const unsigned*)&sB[rn * LDK + kc + 8];
            }
#pragma unroll
            for (int mi = 0; mi < 4; mi++)
#pragma unroll
                for (int nj = 0; nj < 4; nj++)
                    mma_bf16(acc[mi][nj], af[mi][0], af[mi][1], af[mi][2], af[mi][3],
                             bf[nj][0], bf[nj][1]);
        }
        __syncthreads();
    }

    // ---------------- epilogue ----------------
    int om = m0 + wm * 64, on = n0 + wn * 32;
#pragma unroll
    for (int mi = 0; mi < 4; mi++) {
#pragma unroll
        for (int nj = 0; nj < 4; nj++) {
            int ne = on + nj * 8 + thc * 2;
#pragma unroll
            for (int rr = 0; rr < 2; rr++) {
                int o = om + mi * 16 + g + rr * 8;
                float v0 = acc[mi][nj][rr * 2], v1 = acc[mi][nj][rr * 2 + 1];
                if (mode == 0) {
                    float s = P0[o], h = P1[o];
                    OutH[(long long)ne * ldo + o] = __float2bfloat16(v0 * s + h);
                    OutH[(long long)(ne + 1) * ldo + o] = __float2bfloat16(v1 * s + h);
                } else if (mode == 4) {
                    float bia = P0[o];
                    OutH[(long long)ne * ldo + o] = __float2bfloat16(geluf(v0 + bia));
                    OutH[(long long)(ne + 1) * ldo + o] = __float2bfloat16(geluf(v1 + bia));
                } else if (mode == 2) {
                    float bia = P0[o];
                    int win = ne >> 6, j = ne & 63;
                    int s = o >> 8, rr2 = o & 255, hh = rr2 >> 6, d = rr2 & 63;
                    long long idx = ((((long long)win * 3 + s) * 4 + hh) * 64 + d) * 64 + j;
                    float2 st = make_float2(v0 + bia, v1 + bia);
                    *(float2*)&OutF[idx] = st;
                } else if (mode == 3) {
                    float bia = P0[o];
                    int win = ne >> 6, j = ne & 63;
                    int b = win >> 6, widx = win & 63;
                    int h = ((widx >> 3) << 3) + (j >> 3);
                    int w = ((widx & 7) << 3) + (j & 7);
                    long long idx = (long long)b * CHW + (long long)o * HW + h * 64 + w;
                    float2 r = *(const float2*)&Res[idx];
                    float2 st = make_float2(v0 + bia + r.x, v1 + bia + r.y);
                    *(float2*)&OutF[idx] = st;
                } else { // 1, 5
                    float bia = P0[o];
                    int b = ne >> 12, pix = ne & 4095;
                    long long idx = (long long)b * CHW + (long long)o * HW + pix;
                    float2 r = *(const float2*)&Res[idx];
                    float2 st = make_float2(v0 + bia + r.x, v1 + bia + r.y);
                    *(float2*)&OutF[idx] = st;
                }
            }
        }
    }
}

// ---------------- depthwise 3x3 + folded BN2, token-major bf16 ----------------
// tile: 8 wide x 4 high pixels. smem neighborhood 10x6 x 256ch bf16 = 30720B.
__global__ __launch_bounds__(256) void k_dw(const __nv_bfloat16* __restrict__ in,
                                            const float* __restrict__ w,
                                            __nv_bfloat16* __restrict__ out) {
    __shared__ __nv_bfloat16 s[60 * 256];
    int tid = threadIdx.x;
    int w0 = blockIdx.x * 8, h0 = blockIdx.y * 4, b = blockIdx.z;
    for (int i = tid; i < 60 * 32; i += 256) {
        int p = i >> 5, u = i & 31;
        int dy = p / 10, dx = p % 10;
        int gy = h0 + dy - 1, gx = w0 + dx - 1;
        uint4 v = make_uint4(0, 0, 0, 0);
        if (gy >= 0 && gy < 64 && gx >= 0 && gx < 64)
            v = *(const uint4*)&in[((long long)(b * 4096 + gy * 64 + gx)) * 256 + u * 8];
        *(uint4*)&s[p * 256 + u * 8] = v;
    }
    __syncthreads();
    int wid = tid >> 5, lane = tid & 31, c0 = lane * 8;
    float wgt[9][8], sc[8], sh[8];
#pragma unroll
    for (int cc = 0; cc < 8; cc++) {
#pragma unroll
        for (int t = 0; t < 9; t++) wgt[t][cc] = w[(c0 + cc) * 9 + t];
        sc[cc] = g_bn2s[c0 + cc];
        sh[cc] = g_bn2h[c0 + cc];
    }
#pragma unroll
    for (int pp = 0; pp < 4; pp++) {
        int pix = wid * 4 + pp;
        int dy = pix >> 3, dx = pix & 7;
        float av[8] = {0.f, 0.f, 0.f, 0.f, 0.f, 0.f, 0.f, 0.f};
#pragma unroll
        for (int ky = 0; ky < 3; ky++)
#pragma unroll
            for (int kx = 0; kx < 3; kx++) {
                uint4 pv = *(const uint4*)&s[((dy + ky) * 10 + (dx + kx)) * 256 + c0];
                const __nv_bfloat162* h2 = (const __nv_bfloat162*)&pv;
#pragma unroll
                for (int q = 0; q < 4; q++) {
                    float2 f = __bfloat1622float2(h2[q]);
                    av[q * 2] = fmaf(wgt[ky * 3 + kx][q * 2], f.x, av[q * 2]);
                    av[q * 2 + 1] = fmaf(wgt[ky * 3 + kx][q * 2 + 1], f.y, av[q * 2 + 1]);
                }
            }
        __nv_bfloat16 ov[8];
#pragma unroll
        for (int cc = 0; cc < 8; cc++) ov[cc] = __float2bfloat16(av[cc] * sc[cc] + sh[cc]);
        *(uint4*)&out[((long long)(b * 4096 + (h0 + dy) * 64 + (w0 + dx))) * 256 + c0] = *(uint4*)ov;
    }
}

// ---------------- LayerNorm over C=256 -> token-major bf16 output ----------------
// mode 0: window-ordered tokens (block = window), mode 1: row-ordered (block = (b,h))
__global__ void k_ln(const float* __restrict__ xin, const float* __restrict__ g,
                     const float* __restrict__ bta, __nv_bfloat16* __restrict__ out, int mode)
{
    extern __shared__ float sm[];
    float* s = sm;              // 256*65 = 16640
    float* red = sm + 16640;    // 512
    float* mu = red + 512;      // 64
    float* rs = mu + 64;        // 64
    int tid = threadIdx.x;
    int blk = blockIdx.x;
    int b = blk >> 6, q = blk & 63;

    for (int i = tid; i < 16384; i += 256) {
        int c = i >> 6, tok = i & 63;
        long long sp;
        if (mode == 0)
            sp = (long long)b * CHW + (long long)c * HW +
                 (((q >> 3) << 3) + (tok >> 3)) * 64 + ((q & 7) << 3) + (tok & 7);
        else
            sp = (long long)b * CHW + (long long)c * HW + q * 64 + tok;
        s[c * 65 + tok] = xin[sp];
    }
    __syncthreads();
    {
        int tok = tid & 63, part = tid >> 6;
        float sum = 0.f, sq = 0.f;
        for (int c = part * 64; c < part * 64 + 64; c++) {
            float v = s[c * 65 + tok];
            sum += v; sq += v * v;
        }
        red[tid] = sum;
        red[256 + tid] = sq;
    }
    __syncthreads();
    if (tid < 64) {
        float S = red[tid] + red[64 + tid] + red[128 + tid] + red[192 + tid];
        float Q = red[256 + tid] + red[320 + tid] + red[384 + tid] + red[448 + tid];
        float m = S * 0.00390625f;
        float var = Q * 0.00390625f - m * m;
        mu[tid] = m;
        rs[tid] = rsqrtf(var + EPSV);
    }
    __syncthreads();
    long long ob = (long long)blk * 16384;
    for (int i = tid; i < 16384; i += 256) {
        int t2 = i >> 8, c = i & 255;
        out[ob + i] = __float2bfloat16((s[c * 65 + t2] - mu[t2]) * rs[t2] * g[c] + bta[c]);
    }
}

// ---------------- attention: one block per (window, head); bf16 token-major out ----
__global__ __launch_bounds__(256) void k_attn() {
    extern __shared__ float sm[];
    float* qs = sm;                 // [d][tok], 4096
    float* ks = sm + 4096;          // 4096
    float* vs = sm + 8192;          // [d*65+tok], 4160 (padded)
    float* ss = sm + 12352;         // [i*65+j], 4160 (padded)
    int tid = threadIdx.x;
    int win = blockIdx.x, hh = blockIdx.y;
    long long bq = (((long long)win * 3 + 0) * 4 + hh) * 4096;
    long long bk = (((long long)win * 3 + 1) * 4 + hh) * 4096;
    long long bv = (((long long)win * 3 + 2) * 4 + hh) * 4096;
    for (int i = tid; i < 1024; i += 256) {
        ((float4*)qs)[i] = *(const float4*)&g_qkv[bq + (long long)i * 4];
        ((float4*)ks)[i] = *(const float4*)&g_qkv[bk + (long long)i * 4];
    }
    for (int i = tid; i < 4096; i += 256)
        vs[(i >> 6) * 65 + (i & 63)] = g_qkv[bv + i];
    __syncthreads();

    int ti = tid >> 4, tj = tid & 15;
    int i0 = ti * 4, j0 = tj * 4;
    {
        float acc[4][4];
#pragma unroll
        for (int r = 0; r < 4; r++)
#pragma unroll
            for (int c = 0; c < 4; c++) acc[r][c] = 0.f;
        for (int d = 0; d < 64; d++) {
            float4 qv = *(float4*)&qs[d * 64 + i0];
            float4 kv = *(float4*)&ks[d * 64 + j0];
            float qa[4] = {qv.x, qv.y, qv.z, qv.w};
            float ka[4] = {kv.x, kv.y, kv.z, kv.w};
#pragma unroll
            for (int r = 0; r < 4; r++)
#pragma unroll
                for (int c = 0; c < 4; c++) acc[r][c] = fmaf(qa[r], ka[c], acc[r][c]);
        }
#pragma unroll
        for (int r = 0; r < 4; r++)
#pragma unroll
            for (int c = 0; c < 4; c++)
                ss[(i0 + r) * 65 + j0 + c] = acc[r][c] * 0.125f;
    }
    __syncthreads();
    if (tid < 64) {
        float mx = -3.4e38f;
        for (int j = 0; j < 64; j++) mx = fmaxf(mx, ss[tid * 65 + j]);
        float sum = 0.f;
        for (int j = 0; j < 64; j++) {
            float e = expf(ss[tid * 65 + j] - mx);
            ss[tid * 65 + j] = e;
            sum += e;
        }
        float inv = 1.f / sum;
        for (int j = 0; j < 64; j++) ss[tid * 65 + j] *= inv;
    }
    __syncthreads();
    {
        float acc[4][4];
#pragma unroll
        for (int r = 0; r < 4; r++)
#pragma unroll
            for (int c = 0; c < 4; c++) acc[r][c] = 0.f;
        for (int j = 0; j < 64; j++) {
            float p[4], vv[4];
#pragma unroll
            for (int r = 0; r < 4; r++) p[r] = ss[(i0 + r) * 65 + j];
#pragma unroll
            for (int c = 0; c < 4; c++) vv[c] = vs[(j0 + c) * 65 + j];
#pragma unroll
            for (int r = 0; r < 4; r++)
#pragma unroll
                for (int c = 0; c < 4; c++) acc[r][c] = fmaf(p[r], vv[c], acc[r][c]);
        }
#pragma unroll
        for (int r = 0; r < 4; r++) {
            long long oi = ((long long)win * 64 + i0 + r) * 256 + hh * 64 + j0;
            __nv_bfloat162 p0 = __floats2bfloat162_rn(acc[r][0], acc[r][1]);
            __nv_bfloat162 p1 = __floats2bfloat162_rn(acc[r][2], acc[r][3]);
            *(__nv_bfloat162*)&gb_tok[oi] = p0;
            *(__nv_bfloat162*)&gb_tok[oi + 2] = p1;
        }
    }
}

// ---------------- host ----------------
extern "C" void kernel_launch(void* const* d_in, const int* in_sizes, int n_in,
                              void* d_out, int out_size) {
    const float* x       = (const float*)d_in[0];
    const float* conv1_w = (const float*)d_in[1];
    const float* conv1_b = (const float*)d_in[2];
    const float* bn1_g   = (const float*)d_in[3];
    const float* bn1_b   = (const float*)d_in[4];
    const float* bn1_m   = (const float*)d_in[5];
    const float* bn1_v   = (const float*)d_in[6];
    const float* dw_w    = (const float*)d_in[7];
    const float* dw_b    = (const float*)d_in[8];
    const float* bn2_g   = (const float*)d_in[9];
    const float* bn2_b   = (const float*)d_in[10];
    const float* bn2_m   = (const float*)d_in[11];
    const float* bn2_v   = (const float*)d_in[12];
    const float* conv3_w = (const float*)d_in[13];
    const float* conv3_b = (const float*)d_in[14];
    const float* ln1_g   = (const float*)d_in[15];
    const float* ln1_b   = (const float*)d_in[16];
    const float* qkv_w   = (const float*)d_in[17];
    const float* qkv_b   = (const float*)d_in[18];
    const float* proj_w  = (const float*)d_in[19];
    const float* proj_b  = (const float*)d_in[20];
    const float* ln2_g   = (const float*)d_in[21];
    const float* ln2_b   = (const float*)d_in[22];
    const float* mlp_w1  = (const float*)d_in[23];
    const float* mlp_b1  = (const float*)d_in[24];
    const float* mlp_w2  = (const float*)d_in[25];
    const float* mlp_b2  = (const float*)d_in[26];

    float *x1, *x2, *qkv, *bn1s, *bn1h;
    __nv_bfloat16 *xt, *ha, *hb, *tok, *t1, *wb;
    cudaGetSymbolAddress((void**)&x1,  g_x1);
    cudaGetSymbolAddress((void**)&x2,  g_x2);
    cudaGetSymbolAddress((void**)&qkv, g_qkv);
    cudaGetSymbolAddress((void**)&bn1s, g_bn1s);
    cudaGetSymbolAddress((void**)&bn1h, g_bn1h);
    cudaGetSymbolAddress((void**)&xt,  gb_xt);
    cudaGetSymbolAddress((void**)&ha,  gb_a);
    cudaGetSymbolAddress((void**)&hb,  gb_b);
    cudaGetSymbolAddress((void**)&tok, gb_tok);
    cudaGetSymbolAddress((void**)&t1,  gb_t1);
    cudaGetSymbolAddress((void**)&wb,  gb_w);

    const int smemLN = 17280 * 4;  // 69120 B
    const int smemAT = 16512 * 4;  // 66048 B
    cudaFuncSetAttribute(k_ln,   cudaFuncAttributeMaxDynamicSharedMemorySize, smemLN);
    cudaFuncSetAttribute(k_attn, cudaFuncAttributeMaxDynamicSharedMemorySize, smemAT);

    // weight bf16 offsets
    __nv_bfloat16* w_c1  = wb;            // 65536
    __nv_bfloat16* w_c3  = wb + 65536;    // 65536
    __nv_bfloat16* w_qkv = wb + 131072;   // 196608
    __nv_bfloat16* w_pr  = wb + 327680;   // 65536
    __nv_bfloat16* w_m1  = wb + 393216;   // 262144
    __nv_bfloat16* w_m2  = wb + 655360;   // 262144

    // 1. BN folding + weight conversion + x transpose
    k_prep<<<1, 256>>>(conv1_b, bn1_g, bn1_b, bn1_m, bn1_v,
                       dw_b, bn2_g, bn2_b, bn2_m, bn2_v);
    k_cvt<<<256, 256>>>(conv1_w, w_c1, 65536);
    k_cvt<<<256, 256>>>(conv3_w, w_c3, 65536);
    k_cvt<<<768, 256>>>(qkv_w,  w_qkv, 196608);
    k_cvt<<<256, 256>>>(proj_w, w_pr, 65536);
    k_cvt<<<1024, 256>>>(mlp_w1, w_m1, 262144);
    k_cvt<<<1024, 256>>>(mlp_w2, w_m2, 262144);
    k_tx<<<dim3(128, 8, 16), 256>>>(x, xt);

    // 2. conv1 (1x1) + BN1 -> ha bf16 token-major
    k_mm<<<dim3(2, 512), 256>>>(w_c1, xt, 256, 0, bn1s, bn1h, nullptr, nullptr, ha, 256);
    // 3. depthwise 3x3 + BN2 -> hb bf16 token-major
    k_dw<<<dim3(8, 16, 16), 256>>>(ha, dw_w, hb);
    // 4. conv3 (1x1) + bias + residual(x) -> x1 fp32 NCHW
    k_mm<<<dim3(2, 512), 256>>>(w_c3, hb, 256, 1, conv3_b, nullptr, x, x1, nullptr, 0);
    // 5. LN1 (window-ordered) -> tok bf16
    k_ln<<<1024, 256, smemLN>>>(x1, ln1_g, ln1_b, tok, 0);
    // 6. QKV -> g_qkv fp32 scatter
    k_mm<<<dim3(6, 512), 256>>>(w_qkv, tok, 256, 2, qkv_b, nullptr, nullptr, qkv, nullptr, 0);
    // 7. attention -> tok bf16 (attno)
    k_attn<<<dim3(1024, 4), 256, smemAT>>>();
    // 8. proj + residual(x1) -> x2 fp32 NCHW (window reverse)
    k_mm<<<dim3(2, 512), 256>>>(w_pr, tok, 256, 3, proj_b, nullptr, x1, x2, nullptr, 0);
    // 9. LN2 (row-ordered) -> tok bf16
    k_ln<<<1024, 256, smemLN>>>(x2, ln2_g, ln2_b, tok, 1);
    // 10. MLP1 + GELU -> t1 bf16 [tok][1024]
    k_mm<<<dim3(8, 512), 256>>>(w_m1, tok, 256, 4, mlp_b1, nullptr, nullptr, nullptr, t1, 1024);
    // 11. MLP2 + bias + residual(x2) -> d_out fp32 NCHW
    k_mm<<<dim3(2, 512), 256>>>(w_m2, t1, 1024, 5, mlp_b2, nullptr, x2, (float*)d_out, nullptr, 0);
}

// round 8
// speedup vs baseline: 2.5545x; 1.0083x over previous
#include <cuda_runtime.h>
#include <cuda_bf16.h>
#include <math.h>

#define HW 4096
#define CHW 1048576
#define EPSV 1e-5f
#define LDK 40   // padded smem row stride in halves (conflict-free for pad=8)

// ---------------- scratch (device globals; no runtime allocation) ----------------
__device__ float g_bn1s[256], g_bn1h[256], g_bn2s[256], g_bn2h[256];
__device__ float g_x1[16777216];               // conv residual sum, NCHW fp32
__device__ float g_x2[16777216];               // attn residual sum, NCHW fp32
__device__ float g_qkv[50331648];              // [win][3][4][d=64][tok=64] fp32
__device__ __nv_bfloat16 gb_xt[16777216];      // x token-major bf16 [tok][256]
__device__ __nv_bfloat16 gb_a[16777216];       // h1 token-major bf16
__device__ __nv_bfloat16 gb_b[16777216];       // h2 token-major bf16
__device__ __nv_bfloat16 gb_tok[16777216];     // tln / attno token-major bf16 (sequential reuse)
__device__ __nv_bfloat16 gb_t1[67108864];      // mlp hidden bf16 [tok][1024]
__device__ __nv_bfloat16 gb_w[917504];         // all weights bf16

__device__ __forceinline__ float geluf(float x) {
    return 0.5f * x * (1.0f + erff(x * 0.7071067811865476f));
}

__device__ __forceinline__ void mma_bf16(float* c, unsigned a0, unsigned a1,
                                         unsigned a2, unsigned a3,
                                         unsigned b0, unsigned b1) {
    asm volatile(
        "mma.sync.aligned.m16n8k16.row.col.f32.bf16.bf16.f32 "
        "{%0,%1,%2,%3}, {%4,%5,%6,%7}, {%8,%9}, {%0,%1,%2,%3};\n"
        : "+f"(c[0]), "+f"(c[1]), "+f"(c[2]), "+f"(c[3])
        : "r"(a0), "r"(a1), "r"(a2), "r"(a3), "r"(b0), "r"(b1));
}

// ---------------- prep: fold conv bias + BN into scale/shift ----------------
__global__ void k_prep(const float* c1b, const float* g1, const float* b1,
                       const float* m1, const float* v1, const float* dwb,
                       const float* g2, const float* b2, const float* m2, const float* v2) {
    int c = threadIdx.x;
    float inv1 = g1[c] * rsqrtf(v1[c] + EPSV);
    g_bn1s[c] = inv1;
    g_bn1h[c] = c1b[c] * inv1 + b1[c] - m1[c] * inv1;
    float inv2 = g2[c] * rsqrtf(v2[c] + EPSV);
    g_bn2s[c] = inv2;
    g_bn2h[c] = dwb[c] * inv2 + b2[c] - m2[c] * inv2;
}

// ---------------- fp32 -> bf16 convert ----------------
__global__ void k_cvt(const float* __restrict__ s, __nv_bfloat16* __restrict__ d, int n) {
    int i = blockIdx.x * 256 + threadIdx.x;
    if (i < n) d[i] = __float2bfloat16(s[i]);
}

// ---------------- x NCHW fp32 -> token-major bf16 transpose ----------------
__global__ __launch_bounds__(256) void k_tx(const float* __restrict__ x,
                                            __nv_bfloat16* __restrict__ xt) {
    __shared__ float s[32][33];
    int b = blockIdx.z, cg = blockIdx.y * 32, pg = blockIdx.x * 32;
    int tid = threadIdx.x;
    for (int i = tid; i < 1024; i += 256) {
        int c = i >> 5, p = i & 31;
        s[c][p] = x[(long long)b * CHW + (long long)(cg + c) * HW + pg + p];
    }
    __syncthreads();
    for (int i = tid; i < 1024; i += 256) {
        int p = i >> 5, c = i & 31;
        xt[((long long)(b * 4096 + pg + p)) * 256 + cg + c] = __float2bfloat16(s[c][p]);
    }
}

// ---------------- unified bf16 tensor-core GEMM ----------------
// Out[o,n] = sum_k A[o,k] * B[n,k], A bf16 [M,K] row-major, B bf16 token-major [N,K].
// Tiles: BM=128, BN=128, BK=32. 8 warps (2x4), warp tile 64x32, mma m16n8k16.
// modes: 0 conv1 (affine P0/P1 -> bf16 OutH[n*ldo+o])
//        1 conv3 (+P0 bias + Res NCHW -> fp32 OutF NCHW)
//        2 qkv   (+P0 -> fp32 g_qkv scatter)
//        3 proj  (+P0 + Res x1, window-reverse -> fp32 OutF NCHW)
//        4 mlp1  (gelu(v+P0) -> bf16 OutH[n*ldo+o])
//        5 mlp2  (+P0 + Res x2 -> fp32 OutF NCHW)
__global__ __launch_bounds__(256) void k_mm(
    const __nv_bfloat16* __restrict__ A, const __nv_bfloat16* __restrict__ B,
    int K, int mode, const float* __restrict__ P0, const float* __restrict__ P1,
    const float* __restrict__ Res, float* __restrict__ OutF,
    __nv_bfloat16* __restrict__ OutH, int ldo)
{
    __shared__ __nv_bfloat16 sA[128 * LDK];
    __shared__ __nv_bfloat16 sB[128 * LDK];
    int tid = threadIdx.x, wid = tid >> 5, lane = tid & 31;
    int m0 = blockIdx.x * 128, n0 = blockIdx.y * 128;
    int wm = wid >> 2, wn = wid & 3;           // warp grid 2x4
    int g = lane >> 2, thc = lane & 3;

    float acc[4][4][4];
#pragma unroll
    for (int i = 0; i < 4; i++)
#pragma unroll
        for (int j = 0; j < 4; j++)
#pragma unroll
            for (int r = 0; r < 4; r++) acc[i][j][r] = 0.f;

    int lrow = tid >> 1, lq8 = (tid & 1) * 16;   // halves offset 0 or 16
    const __nv_bfloat16* pa = A + (long long)(m0 + lrow) * K + lq8;
    const __nv_bfloat16* pb = B + (long long)(n0 + lrow) * K + lq8;
    int sOff = lrow * LDK + lq8;

    const int KT = K >> 5;
    uint4 ra0 = *(const uint4*)(pa);
    uint4 ra1 = *(const uint4*)(pa + 8);
    uint4 rb0 = *(const uint4*)(pb);
    uint4 rb1 = *(const uint4*)(pb + 8);

    for (int kt = 0; kt < KT; kt++) {
        *(uint4*)&sA[sOff] = ra0;
        *(uint4*)&sA[sOff + 8] = ra1;
        *(uint4*)&sB[sOff] = rb0;
        *(uint4*)&sB[sOff + 8] = rb1;
        __syncthreads();
        if (kt + 1 < KT) {
            const __nv_bfloat16* qa = pa + (kt + 1) * 32;
            const __nv_bfloat16* qb = pb + (kt + 1) * 32;
            ra0 = *(const uint4*)(qa);  ra1 = *(const uint4*)(qa + 8);
            rb0 = *(const uint4*)(qb);  rb1 = *(const uint4*)(qb + 8);
        }
#pragma unroll
        for (int ks = 0; ks < 2; ks++) {
            unsigned af[4][4], bf[4][2];
            int kc = ks * 16 + thc * 2;
#pragma unroll
            for (int mi = 0; mi < 4; mi++) {
                int rb_ = wm * 64 + mi * 16 + g;
                af[mi][0] = *(const unsigned*)&sA[rb_ * LDK + kc];
                af[mi][1] = *(const unsigned*)&sA[(rb_ + 8) * LDK + kc];
                af[mi][2] = *(const unsigned*)&sA[rb_ * LDK + kc + 8];
                af[mi][3] = *(const unsigned*)&sA[(rb_ + 8) * LDK + kc + 8];
            }
#pragma unroll
            for (int nj = 0; nj < 4; nj++) {
                int rn = wn * 32 + nj * 8 + g;
                bf[nj][0] = *(const unsigned*)&sB[rn * LDK + kc];
                bf[nj][1] = *(const unsigned*)&sB[rn * LDK + kc + 8];
            }
#pragma unroll
            for (int mi = 0; mi < 4; mi++)
#pragma unroll
                for (int nj = 0; nj < 4; nj++)
                    mma_bf16(acc[mi][nj], af[mi][0], af[mi][1], af[mi][2], af[mi][3],
                             bf[nj][0], bf[nj][1]);
        }
        __syncthreads();
    }

    // ---------------- epilogue ----------------
    int om = m0 + wm * 64, on = n0 + wn * 32;
#pragma unroll
    for (int mi = 0; mi < 4; mi++) {
#pragma unroll
        for (int nj = 0; nj < 4; nj++) {
            int ne = on + nj * 8 + thc * 2;
#pragma unroll
            for (int rr = 0; rr < 2; rr++) {
                int o = om + mi * 16 + g + rr * 8;
                float v0 = acc[mi][nj][rr * 2], v1 = acc[mi][nj][rr * 2 + 1];
                if (mode == 0) {
                    float s = P0[o], h = P1[o];
                    OutH[(long long)ne * ldo + o] = __float2bfloat16(v0 * s + h);
                    OutH[(long long)(ne + 1) * ldo + o] = __float2bfloat16(v1 * s + h);
                } else if (mode == 4) {
                    float bia = P0[o];
                    OutH[(long long)ne * ldo + o] = __float2bfloat16(geluf(v0 + bia));
                    OutH[(long long)(ne + 1) * ldo + o] = __float2bfloat16(geluf(v1 + bia));
                } else if (mode == 2) {
                    float bia = P0[o];
                    int win = ne >> 6, j = ne & 63;
                    int s = o >> 8, rr2 = o & 255, hh = rr2 >> 6, d = rr2 & 63;
                    long long idx = ((((long long)win * 3 + s) * 4 + hh) * 64 + d) * 64 + j;
                    float2 st = make_float2(v0 + bia, v1 + bia);
                    *(float2*)&OutF[idx] = st;
                } else if (mode == 3) {
                    float bia = P0[o];
                    int win = ne >> 6, j = ne & 63;
                    int b = win >> 6, widx = win & 63;
                    int h = ((widx >> 3) << 3) + (j >> 3);
                    int w = ((widx & 7) << 3) + (j & 7);
                    long long idx = (long long)b * CHW + (long long)o * HW + h * 64 + w;
                    float2 r = *(const float2*)&Res[idx];
                    float2 st = make_float2(v0 + bia + r.x, v1 + bia + r.y);
                    *(float2*)&OutF[idx] = st;
                } else { // 1, 5
                    float bia = P0[o];
                    int b = ne >> 12, pix = ne & 4095;
                    long long idx = (long long)b * CHW + (long long)o * HW + pix;
                    float2 r = *(const float2*)&Res[idx];
                    float2 st = make_float2(v0 + bia + r.x, v1 + bia + r.y);
                    *(float2*)&OutF[idx] = st;
                }
            }
        }
    }
}

// ---------------- depthwise 3x3 + folded BN2, token-major bf16 ----------------
// tile: 8 wide x 4 high pixels. smem neighborhood 10x6 x 256ch bf16 = 30720B.
__global__ __launch_bounds__(256) void k_dw(const __nv_bfloat16* __restrict__ in,
                                            const float* __restrict__ w,
                                            __nv_bfloat16* __restrict__ out) {
    __shared__ __nv_bfloat16 s[60 * 256];
    int tid = threadIdx.x;
    int w0 = blockIdx.x * 8, h0 = blockIdx.y * 4, b = blockIdx.z;
    for (int i = tid; i < 60 * 32; i += 256) {
        int p = i >> 5, u = i & 31;
        int dy = p / 10, dx = p % 10;
        int gy = h0 + dy - 1, gx = w0 + dx - 1;
        uint4 v = make_uint4(0, 0, 0, 0);
        if (gy >= 0 && gy < 64 && gx >= 0 && gx < 64)
            v = *(const uint4*)&in[((long long)(b * 4096 + gy * 64 + gx)) * 256 + u * 8];
        *(uint4*)&s[p * 256 + u * 8] = v;
    }
    __syncthreads();
    int wid = tid >> 5, lane = tid & 31, c0 = lane * 8;
    float wgt[9][8], sc[8], sh[8];
#pragma unroll
    for (int cc = 0; cc < 8; cc++) {
#pragma unroll
        for (int t = 0; t < 9; t++) wgt[t][cc] = w[(c0 + cc) * 9 + t];
        sc[cc] = g_bn2s[c0 + cc];
        sh[cc] = g_bn2h[c0 + cc];
    }
#pragma unroll
    for (int pp = 0; pp < 4; pp++) {
        int pix = wid * 4 + pp;
        int dy = pix >> 3, dx = pix & 7;
        float av[8] = {0.f, 0.f, 0.f, 0.f, 0.f, 0.f, 0.f, 0.f};
#pragma unroll
        for (int ky = 0; ky < 3; ky++)
#pragma unroll
            for (int kx = 0; kx < 3; kx++) {
                uint4 pv = *(const uint4*)&s[((dy + ky) * 10 + (dx + kx)) * 256 + c0];
                const __nv_bfloat162* h2 = (const __nv_bfloat162*)&pv;
#pragma unroll
                for (int q = 0; q < 4; q++) {
                    float2 f = __bfloat1622float2(h2[q]);
                    av[q * 2] = fmaf(wgt[ky * 3 + kx][q * 2], f.x, av[q * 2]);
                    av[q * 2 + 1] = fmaf(wgt[ky * 3 + kx][q * 2 + 1], f.y, av[q * 2 + 1]);
                }
            }
        __nv_bfloat16 ov[8];
#pragma unroll
        for (int cc = 0; cc < 8; cc++) ov[cc] = __float2bfloat16(av[cc] * sc[cc] + sh[cc]);
        *(uint4*)&out[((long long)(b * 4096 + (h0 + dy) * 64 + (w0 + dx))) * 256 + c0] = *(uint4*)ov;
    }
}

// ---------------- LayerNorm over C=256 -> token-major bf16 output ----------------
// mode 0: window-ordered tokens (block = window), mode 1: row-ordered (block = (b,h))
__global__ void k_ln(const float* __restrict__ xin, const float* __restrict__ g,
                     const float* __restrict__ bta, __nv_bfloat16* __restrict__ out, int mode)
{
    extern __shared__ float sm[];
    float* s = sm;              // 256*65 = 16640
    float* red = sm + 16640;    // 512
    float* mu = red + 512;      // 64
    float* rs = mu + 64;        // 64
    int tid = threadIdx.x;
    int blk = blockIdx.x;
    int b = blk >> 6, q = blk & 63;

    for (int i = tid; i < 16384; i += 256) {
        int c = i >> 6, tok = i & 63;
        long long sp;
        if (mode == 0)
            sp = (long long)b * CHW + (long long)c * HW +
                 (((q >> 3) << 3) + (tok >> 3)) * 64 + ((q & 7) << 3) + (tok & 7);
        else
            sp = (long long)b * CHW + (long long)c * HW + q * 64 + tok;
        s[c * 65 + tok] = xin[sp];
    }
    __syncthreads();
    {
        int tok = tid & 63, part = tid >> 6;
        float sum = 0.f, sq = 0.f;
        for (int c = part * 64; c < part * 64 + 64; c++) {
            float v = s[c * 65 + tok];
            sum += v; sq += v * v;
        }
        red[tid] = sum;
        red[256 + tid] = sq;
    }
    __syncthreads();
    if (tid < 64) {
        float S = red[tid] + red[64 + tid] + red[128 + tid] + red[192 + tid];
        float Q = red[256 + tid] + red[320 + tid] + red[384 + tid] + red[448 + tid];
        float m = S * 0.00390625f;
        float var = Q * 0.00390625f - m * m;
        mu[tid] = m;
        rs[tid] = rsqrtf(var + EPSV);
    }
    __syncthreads();
    long long ob = (long long)blk * 16384;
    for (int i = tid; i < 16384; i += 256) {
        int t2 = i >> 8, c = i & 255;
        out[ob + i] = __float2bfloat16((s[c * 65 + t2] - mu[t2]) * rs[t2] * g[c] + bta[c]);
    }
}

// ---------------- attention: one block per (window, head); bf16 token-major out ----
__global__ __launch_bounds__(256) void k_attn() {
    extern __shared__ float sm[];
    float* qs = sm;                 // [d][tok], 4096
    float* ks = sm + 4096;          // 4096
    float* vs = sm + 8192;          // [d*65+tok], 4160 (padded)
    float* ss = sm + 12352;         // [i*65+j], 4160 (padded)
    int tid = threadIdx.x;
    int win = blockIdx.x, hh = blockIdx.y;
    long long bq = (((long long)win * 3 + 0) * 4 + hh) * 4096;
    long long bk = (((long long)win * 3 + 1) * 4 + hh) * 4096;
    long long bv = (((long long)win * 3 + 2) * 4 + hh) * 4096;
    for (int i = tid; i < 1024; i += 256) {
        ((float4*)qs)[i] = *(const float4*)&g_qkv[bq + (long long)i * 4];
        ((float4*)ks)[i] = *(const float4*)&g_qkv[bk + (long long)i * 4];
    }
    for (int i = tid; i < 4096; i += 256)
        vs[(i >> 6) * 65 + (i & 63)] = g_qkv[bv + i];
    __syncthreads();

    int ti = tid >> 4, tj = tid & 15;
    int i0 = ti * 4, j0 = tj * 4;
    {
        float acc[4][4];
#pragma unroll
        for (int r = 0; r < 4; r++)
#pragma unroll
            for (int c = 0; c < 4; c++) acc[r][c] = 0.f;
        for (int d = 0; d < 64; d++) {
            float4 qv = *(float4*)&qs[d * 64 + i0];
            float4 kv = *(float4*)&ks[d * 64 + j0];
            float qa[4] = {qv.x, qv.y, qv.z, qv.w};
            float ka[4] = {kv.x, kv.y, kv.z, kv.w};
#pragma unroll
            for (int r = 0; r < 4; r++)
#pragma unroll
                for (int c = 0; c < 4; c++) acc[r][c] = fmaf(qa[r], ka[c], acc[r][c]);
        }
#pragma unroll
        for (int r = 0; r < 4; r++)
#pragma unroll
            for (int c = 0; c < 4; c++)
                ss[(i0 + r) * 65 + j0 + c] = acc[r][c] * 0.125f;
    }
    __syncthreads();
    if (tid < 64) {
        float mx = -3.4e38f;
        for (int j = 0; j < 64; j++) mx = fmaxf(mx, ss[tid * 65 + j]);
        float sum = 0.f;
        for (int j = 0; j < 64; j++) {
            float e = expf(ss[tid * 65 + j] - mx);
            ss[tid * 65 + j] = e;
            sum += e;
        }
        float inv = 1.f / sum;
        for (int j = 0; j < 64; j++) ss[tid * 65 + j] *= inv;
    }
    __syncthreads();
    {
        float acc[4][4];
#pragma unroll
        for (int r = 0; r < 4; r++)
#pragma unroll
            for (int c = 0; c < 4; c++) acc[r][c] = 0.f;
        for (int j = 0; j < 64; j++) {
            float p[4], vv[4];
#pragma unroll
            for (int r = 0; r < 4; r++) p[r] = ss[(i0 + r) * 65 + j];
#pragma unroll
            for (int c = 0; c < 4; c++) vv[c] = vs[(j0 + c) * 65 + j];
#pragma unroll
            for (int r = 0; r < 4; r++)
#pragma unroll
                for (int c = 0; c < 4; c++) acc[r][c] = fmaf(p[r], vv[c], acc[r][c]);
        }
#pragma unroll
        for (int r = 0; r < 4; r++) {
            long long oi = ((long long)win * 64 + i0 + r) * 256 + hh * 64 + j0;
            __nv_bfloat162 p0 = __floats2bfloat162_rn(acc[r][0], acc[r][1]);
            __nv_bfloat162 p1 = __floats2bfloat162_rn(acc[r][2], acc[r][3]);
            *(__nv_bfloat162*)&gb_tok[oi] = p0;
            *(__nv_bfloat162*)&gb_tok[oi + 2] = p1;
        }
    }
}

// ---------------- host ----------------
extern "C" void kernel_launch(void* const* d_in, const int* in_sizes, int n_in,
                              void* d_out, int out_size) {
    const float* x       = (const float*)d_in[0];
    const float* conv1_w = (const float*)d_in[1];
    const float* conv1_b = (const float*)d_in[2];
    const float* bn1_g   = (const float*)d_in[3];
    const float* bn1_b   = (const float*)d_in[4];
    const float* bn1_m   = (const float*)d_in[5];
    const float* bn1_v   = (const float*)d_in[6];
    const float* dw_w    = (const float*)d_in[7];
    const float* dw_b    = (const float*)d_in[8];
    const float* bn2_g   = (const float*)d_in[9];
    const float* bn2_b   = (const float*)d_in[10];
    const float* bn2_m   = (const float*)d_in[11];
    const float* bn2_v   = (const float*)d_in[12];
    const float* conv3_w = (const float*)d_in[13];
    const float* conv3_b = (const float*)d_in[14];
    const float* ln1_g   = (const float*)d_in[15];
    const float* ln1_b   = (const float*)d_in[16];
    const float* qkv_w   = (const float*)d_in[17];
    const float* qkv_b   = (const float*)d_in[18];
    const float* proj_w  = (const float*)d_in[19];
    const float* proj_b  = (const float*)d_in[20];
    const float* ln2_g   = (const float*)d_in[21];
    const float* ln2_b   = (const float*)d_in[22];
    const float* mlp_w1  = (const float*)d_in[23];
    const float* mlp_b1  = (const float*)d_in[24];
    const float* mlp_w2  = (const float*)d_in[25];
    const float* mlp_b2  = (const float*)d_in[26];

    float *x1, *x2, *qkv, *bn1s, *bn1h;
    __nv_bfloat16 *xt, *ha, *hb, *tok, *t1, *wb;
    cudaGetSymbolAddress((void**)&x1,  g_x1);
    cudaGetSymbolAddress((void**)&x2,  g_x2);
    cudaGetSymbolAddress((void**)&qkv, g_qkv);
    cudaGetSymbolAddress((void**)&bn1s, g_bn1s);
    cudaGetSymbolAddress((void**)&bn1h, g_bn1h);
    cudaGetSymbolAddress((void**)&xt,  gb_xt);
    cudaGetSymbolAddress((void**)&ha,  gb_a);
    cudaGetSymbolAddress((void**)&hb,  gb_b);
    cudaGetSymbolAddress((void**)&tok, gb_tok);
    cudaGetSymbolAddress((void**)&t1,  gb_t1);
    cudaGetSymbolAddress((void**)&wb,  gb_w);

    const int smemLN = 17280 * 4;  // 69120 B
    const int smemAT = 16512 * 4;  // 66048 B
    cudaFuncSetAttribute(k_ln,   cudaFuncAttributeMaxDynamicSharedMemorySize, smemLN);
    cudaFuncSetAttribute(k_attn, cudaFuncAttributeMaxDynamicSharedMemorySize, smemAT);

    // weight bf16 offsets
    __nv_bfloat16* w_c1  = wb;            // 65536
    __nv_bfloat16* w_c3  = wb + 65536;    // 65536
    __nv_bfloat16* w_qkv = wb + 131072;   // 196608
    __nv_bfloat16* w_pr  = wb + 327680;   // 65536
    __nv_bfloat16* w_m1  = wb + 393216;   // 262144
    __nv_bfloat16* w_m2  = wb + 655360;   // 262144

    // 1. BN folding + weight conversion + x transpose
    k_prep<<<1, 256>>>(conv1_b, bn1_g, bn1_b, bn1_m, bn1_v,
                       dw_b, bn2_g, bn2_b, bn2_m, bn2_v);
    k_cvt<<<256, 256>>>(conv1_w, w_c1, 65536);
    k_cvt<<<256, 256>>>(conv3_w, w_c3, 65536);
    k_cvt<<<768, 256>>>(qkv_w,  w_qkv, 196608);
    k_cvt<<<256, 256>>>(proj_w, w_pr, 65536);
    k_cvt<<<1024, 256>>>(mlp_w1, w_m1, 262144);
    k_cvt<<<1024, 256>>>(mlp_w2, w_m2, 262144);
    k_tx<<<dim3(128, 8, 16), 256>>>(x, xt);

    // 2. conv1 (1x1) + BN1 -> ha bf16 token-major
    k_mm<<<dim3(2, 512), 256>>>(w_c1, xt, 256, 0, bn1s, bn1h, nullptr, nullptr, ha, 256);
    // 3. depthwise 3x3 + BN2 -> hb bf16 token-major
    k_dw<<<dim3(8, 16, 16), 256>>>(ha, dw_w, hb);
    // 4. conv3 (1x1) + bias + residual(x) -> x1 fp32 NCHW
    k_mm<<<dim3(2, 512), 256>>>(w_c3, hb, 256, 1, conv3_b, nullptr, x, x1, nullptr, 0);
    // 5. LN1 (window-ordered) -> tok bf16
    k_ln<<<1024, 256, smemLN>>>(x1, ln1_g, ln1_b, tok, 0);
    // 6. QKV -> g_qkv fp32 scatter
    k_mm<<<dim3(6, 512), 256>>>(w_qkv, tok, 256, 2, qkv_b, nullptr, nullptr, qkv, nullptr, 0);
    // 7. attention -> tok bf16 (attno)
    k_attn<<<dim3(1024, 4), 256, smemAT>>>();
    // 8. proj + residual(x1) -> x2 fp32 NCHW (window reverse)
    k_mm<<<dim3(2, 512), 256>>>(w_pr, tok, 256, 3, proj_b, nullptr, x1, x2, nullptr, 0);
    // 9. LN2 (row-ordered) -> tok bf16
    k_ln<<<1024, 256, smemLN>>>(x2, ln2_g, ln2_b, tok, 1);
    // 10. MLP1 + GELU -> t1 bf16 [tok][1024]
    k_mm<<<dim3(8, 512), 256>>>(w_m1, tok, 256, 4, mlp_b1, nullptr, nullptr, nullptr, t1, 1024);
    // 11. MLP2 + bias + residual(x2) -> d_out fp32 NCHW
    k_mm<<<dim3(2, 512), 256>>>(w_m2, t1, 1024, 5, mlp_b2, nullptr, x2, (float*)d_out, nullptr, 0);
}